// round 2
// baseline (speedup 1.0000x reference)
#include <cuda_runtime.h>

// GravityDecoder: per-edge fused gather + linear + log-dist + sigmoid.
// Inputs (metadata order):
//   d_in[0]: z          float32 [N, 128]
//   d_in[1]: edge_index int32   [2, E]   (JAX x64 disabled -> int64 request materializes int32)
//   d_in[2]: W          float32 [128]
//   d_in[3]: b          float32 scalar
// Output: float32 [4, E] = (logits, prob, m_j, dist2) concatenated.

#define WARPS_PER_BLOCK 8
#define THREADS (WARPS_PER_BLOCK * 32)

__global__ __launch_bounds__(THREADS) void gravity_decoder_kernel(
    const float* __restrict__ z,
    const int* __restrict__ edge_index,
    const float* __restrict__ W,
    const float* __restrict__ b_ptr,
    float* __restrict__ out,
    int E)
{
    const int lane   = threadIdx.x & 31;
    const int warp   = (int)((blockIdx.x * (unsigned)blockDim.x + threadIdx.x) >> 5);
    const int nwarps = (int)((gridDim.x * (unsigned)blockDim.x) >> 5);

    const float b = *b_ptr;
    // Each lane owns 4 consecutive feature dims: lane*4 .. lane*4+3
    const float4 w4 = reinterpret_cast<const float4*>(W)[lane];

    float* __restrict__ out_logits = out;
    float* __restrict__ out_prob   = out + (size_t)E;
    float* __restrict__ out_mj     = out + 2 * (size_t)E;
    float* __restrict__ out_d2     = out + 3 * (size_t)E;

    for (int e = warp; e < E; e += nwarps) {
        const int src = edge_index[e];               // row for z_i
        const int dst = edge_index[e + (size_t)E];   // row for z_j

        const float4 zi = reinterpret_cast<const float4*>(z + (size_t)src * 128)[lane];
        const float4 zj = reinterpret_cast<const float4*>(z + (size_t)dst * 128)[lane];

        float mj = zj.x * w4.x + zj.y * w4.y + zj.z * w4.z + zj.w * w4.w;

        float dx = zi.x - zj.x;
        float dy = zi.y - zj.y;
        float dz = zi.z - zj.z;
        float dw = zi.w - zj.w;
        float d2 = dx * dx + dy * dy + dz * dz + dw * dw;

        // Warp tree-reduce both scalars (butterfly -> all lanes hold result)
        #pragma unroll
        for (int off = 16; off > 0; off >>= 1) {
            mj += __shfl_xor_sync(0xffffffffu, mj, off);
            d2 += __shfl_xor_sync(0xffffffffu, d2, off);
        }

        mj += b;
        d2 += 1e-7f;
        const float logit = mj - logf(d2);

        // Spread the 4 scalar stores across lanes 0..3
        if (lane == 0) out_logits[e] = logit;
        else if (lane == 1) out_prob[e] = 1.0f / (1.0f + expf(-logit));
        else if (lane == 2) out_mj[e]   = mj;
        else if (lane == 3) out_d2[e]   = d2;
    }
}

extern "C" void kernel_launch(void* const* d_in, const int* in_sizes, int n_in,
                              void* d_out, int out_size)
{
    const float* z   = (const float*)d_in[0];
    const int*   ei  = (const int*)d_in[1];
    const float* W   = (const float*)d_in[2];
    const float* b   = (const float*)d_in[3];
    float*       out = (float*)d_out;

    const int E = in_sizes[1] / 2;

    int blocks = (E + WARPS_PER_BLOCK - 1) / WARPS_PER_BLOCK;
    if (blocks > 4736) blocks = 4736;

    gravity_decoder_kernel<<<blocks, THREADS>>>(z, ei, W, b, out, E);
}

// round 3
// speedup vs baseline: 2.1116x; 2.1116x over previous
#include <cuda_runtime.h>

// GravityDecoder: per-edge fused gather + linear + log-dist + sigmoid.
// Inputs (metadata order):
//   d_in[0]: z          float32 [N, 128]
//   d_in[1]: edge_index int32   [2, E]
//   d_in[2]: W          float32 [128]
//   d_in[3]: b          float32 scalar
// Output: float32 [4, E] = (logits, prob, m_j, dist2) concatenated.
//
// Layout: 8 lanes per edge (4 edges per warp). Each lane loads 4 float4s
// per z row -> 4x memory-level parallelism per thread, and the warp
// reduction shrinks to a 3-step butterfly shared across 4 edges.

#define WARPS_PER_BLOCK 8
#define THREADS (WARPS_PER_BLOCK * 32)

__global__ __launch_bounds__(THREADS) void gravity_decoder_kernel(
    const float* __restrict__ z,
    const int* __restrict__ edge_index,
    const float* __restrict__ W,
    const float* __restrict__ b_ptr,
    float* __restrict__ out,
    int E)
{
    const int lane   = threadIdx.x & 31;
    const int sub    = lane & 7;        // sublane within 8-lane group
    const int group  = lane >> 3;       // 0..3 : which edge of the 4
    const int warp   = (int)((blockIdx.x * (unsigned)blockDim.x + threadIdx.x) >> 5);
    const int nwarps = (int)((gridDim.x * (unsigned)blockDim.x) >> 5);

    const float b = *b_ptr;

    const float4* __restrict__ Wf4 = reinterpret_cast<const float4*>(W);
    const float4 w0 = Wf4[sub];
    const float4 w1 = Wf4[sub + 8];
    const float4 w2 = Wf4[sub + 16];
    const float4 w3 = Wf4[sub + 24];

    float* __restrict__ out_logits = out;
    float* __restrict__ out_prob   = out + (size_t)E;
    float* __restrict__ out_mj     = out + 2 * (size_t)E;
    float* __restrict__ out_d2     = out + 3 * (size_t)E;

    for (int e4 = warp * 4; e4 < E; e4 += nwarps * 4) {
        const int e      = e4 + group;
        const bool alive = (e < E);
        const int es     = alive ? e : (E - 1);   // safe index for loads

        const int src = edge_index[es];
        const int dst = edge_index[es + (size_t)E];

        const float4* __restrict__ zi4 = reinterpret_cast<const float4*>(z + (size_t)src * 128);
        const float4* __restrict__ zj4 = reinterpret_cast<const float4*>(z + (size_t)dst * 128);

        const float4 a0 = zi4[sub];
        const float4 a1 = zi4[sub + 8];
        const float4 a2 = zi4[sub + 16];
        const float4 a3 = zi4[sub + 24];
        const float4 c0 = zj4[sub];
        const float4 c1 = zj4[sub + 8];
        const float4 c2 = zj4[sub + 16];
        const float4 c3 = zj4[sub + 24];

        float mj = c0.x * w0.x + c0.y * w0.y + c0.z * w0.z + c0.w * w0.w;
        mj      += c1.x * w1.x + c1.y * w1.y + c1.z * w1.z + c1.w * w1.w;
        mj      += c2.x * w2.x + c2.y * w2.y + c2.z * w2.z + c2.w * w2.w;
        mj      += c3.x * w3.x + c3.y * w3.y + c3.z * w3.z + c3.w * w3.w;

        float d2;
        {
            float dx, dy, dz, dw;
            dx = a0.x - c0.x; dy = a0.y - c0.y; dz = a0.z - c0.z; dw = a0.w - c0.w;
            d2  = dx * dx + dy * dy + dz * dz + dw * dw;
            dx = a1.x - c1.x; dy = a1.y - c1.y; dz = a1.z - c1.z; dw = a1.w - c1.w;
            d2 += dx * dx + dy * dy + dz * dz + dw * dw;
            dx = a2.x - c2.x; dy = a2.y - c2.y; dz = a2.z - c2.z; dw = a2.w - c2.w;
            d2 += dx * dx + dy * dy + dz * dz + dw * dw;
            dx = a3.x - c3.x; dy = a3.y - c3.y; dz = a3.z - c3.z; dw = a3.w - c3.w;
            d2 += dx * dx + dy * dy + dz * dz + dw * dw;
        }

        // 3-step butterfly within each 8-lane group (offsets 4,2,1 stay in-group)
        #pragma unroll
        for (int off = 4; off > 0; off >>= 1) {
            mj += __shfl_xor_sync(0xffffffffu, mj, off);
            d2 += __shfl_xor_sync(0xffffffffu, d2, off);
        }

        mj += b;
        d2 += 1e-7f;
        const float logit = mj - __logf(d2);

        if (alive) {
            if (sub == 0)      out_logits[e] = logit;
            else if (sub == 1) out_prob[e]   = __fdividef(1.0f, 1.0f + __expf(-logit));
            else if (sub == 2) out_mj[e]     = mj;
            else if (sub == 3) out_d2[e]     = d2;
        }
    }
}

extern "C" void kernel_launch(void* const* d_in, const int* in_sizes, int n_in,
                              void* d_out, int out_size)
{
    const float* z   = (const float*)d_in[0];
    const int*   ei  = (const int*)d_in[1];
    const float* W   = (const float*)d_in[2];
    const float* b   = (const float*)d_in[3];
    float*       out = (float*)d_out;

    const int E = in_sizes[1] / 2;

    // 4 edges per warp per iteration
    int blocks = (E + WARPS_PER_BLOCK * 4 - 1) / (WARPS_PER_BLOCK * 4);
    if (blocks > 4736) blocks = 4736;

    gravity_decoder_kernel<<<blocks, THREADS>>>(z, ei, W, b, out, E);
}

// round 4
// speedup vs baseline: 2.2066x; 1.0450x over previous
#include <cuda_runtime.h>

// GravityDecoder: per-edge fused gather + linear + log-dist + sigmoid.
// Inputs (metadata order):
//   d_in[0]: z          float32 [N, 128]
//   d_in[1]: edge_index int32   [2, E]
//   d_in[2]: W          float32 [128]
//   d_in[3]: b          float32 scalar
// Output: float32 [4, E] = (logits, prob, m_j, dist2) concatenated.
//
// Layout: 8 lanes per edge (4 edges per warp), index loads software-pipelined
// across grid-stride iterations, occupancy forced to 5 blocks/SM.

#define WARPS_PER_BLOCK 8
#define THREADS (WARPS_PER_BLOCK * 32)

__global__ __launch_bounds__(THREADS, 5) void gravity_decoder_kernel(
    const float* __restrict__ z,
    const int* __restrict__ edge_index,
    const float* __restrict__ W,
    const float* __restrict__ b_ptr,
    float* __restrict__ out,
    int E)
{
    const int lane   = threadIdx.x & 31;
    const int sub    = lane & 7;        // sublane within 8-lane group
    const int group  = lane >> 3;       // 0..3 : which edge of the 4
    const int warp   = (int)((blockIdx.x * (unsigned)blockDim.x + threadIdx.x) >> 5);
    const int nwarps = (int)((gridDim.x * (unsigned)blockDim.x) >> 5);
    const int stride = nwarps * 4;

    const float b = *b_ptr;

    const float4* __restrict__ Wf4 = reinterpret_cast<const float4*>(W);
    const float4 w0 = Wf4[sub];
    const float4 w1 = Wf4[sub + 8];
    const float4 w2 = Wf4[sub + 16];
    const float4 w3 = Wf4[sub + 24];

    float* __restrict__ out_logits = out;
    float* __restrict__ out_prob   = out + (size_t)E;
    float* __restrict__ out_mj     = out + 2 * (size_t)E;
    float* __restrict__ out_d2     = out + 3 * (size_t)E;

    int e4 = warp * 4;
    if (e4 >= E) return;

    // Prologue: load indices for the first iteration
    int e  = e4 + group;
    int es = (e < E) ? e : (E - 1);
    int src = edge_index[es];
    int dst = edge_index[es + (size_t)E];

    for (; e4 < E; e4 += stride) {
        const bool alive = (e4 + group < E);
        const int  ecur  = e4 + group;

        const float4* __restrict__ zi4 = reinterpret_cast<const float4*>(z + (size_t)src * 128);
        const float4* __restrict__ zj4 = reinterpret_cast<const float4*>(z + (size_t)dst * 128);

        // Issue all 8 gathers up front (MLP)
        const float4 a0 = zi4[sub];
        const float4 a1 = zi4[sub + 8];
        const float4 a2 = zi4[sub + 16];
        const float4 a3 = zi4[sub + 24];
        const float4 c0 = zj4[sub];
        const float4 c1 = zj4[sub + 8];
        const float4 c2 = zj4[sub + 16];
        const float4 c3 = zj4[sub + 24];

        // Prefetch next iteration's indices while gathers are in flight
        const int e4n = e4 + stride;
        if (e4n < E) {
            const int en  = e4n + group;
            const int esn = (en < E) ? en : (E - 1);
            src = edge_index[esn];
            dst = edge_index[esn + (size_t)E];
        }

        float mj = c0.x * w0.x + c0.y * w0.y + c0.z * w0.z + c0.w * w0.w;
        mj      += c1.x * w1.x + c1.y * w1.y + c1.z * w1.z + c1.w * w1.w;
        mj      += c2.x * w2.x + c2.y * w2.y + c2.z * w2.z + c2.w * w2.w;
        mj      += c3.x * w3.x + c3.y * w3.y + c3.z * w3.z + c3.w * w3.w;

        float d2;
        {
            float dx, dy, dz, dw;
            dx = a0.x - c0.x; dy = a0.y - c0.y; dz = a0.z - c0.z; dw = a0.w - c0.w;
            d2  = dx * dx + dy * dy + dz * dz + dw * dw;
            dx = a1.x - c1.x; dy = a1.y - c1.y; dz = a1.z - c1.z; dw = a1.w - c1.w;
            d2 += dx * dx + dy * dy + dz * dz + dw * dw;
            dx = a2.x - c2.x; dy = a2.y - c2.y; dz = a2.z - c2.z; dw = a2.w - c2.w;
            d2 += dx * dx + dy * dy + dz * dz + dw * dw;
            dx = a3.x - c3.x; dy = a3.y - c3.y; dz = a3.z - c3.z; dw = a3.w - c3.w;
            d2 += dx * dx + dy * dy + dz * dz + dw * dw;
        }

        // 3-step butterfly within each 8-lane group
        #pragma unroll
        for (int off = 4; off > 0; off >>= 1) {
            mj += __shfl_xor_sync(0xffffffffu, mj, off);
            d2 += __shfl_xor_sync(0xffffffffu, d2, off);
        }

        mj += b;
        d2 += 1e-7f;
        const float logit = mj - __logf(d2);

        if (alive) {
            if (sub == 0)      out_logits[ecur] = logit;
            else if (sub == 1) out_prob[ecur]   = __fdividef(1.0f, 1.0f + __expf(-logit));
            else if (sub == 2) out_mj[ecur]     = mj;
            else if (sub == 3) out_d2[ecur]     = d2;
        }
    }
}

extern "C" void kernel_launch(void* const* d_in, const int* in_sizes, int n_in,
                              void* d_out, int out_size)
{
    const float* z   = (const float*)d_in[0];
    const int*   ei  = (const int*)d_in[1];
    const float* W   = (const float*)d_in[2];
    const float* b   = (const float*)d_in[3];
    float*       out = (float*)d_out;

    const int E = in_sizes[1] / 2;

    int blocks = (E + WARPS_PER_BLOCK * 4 - 1) / (WARPS_PER_BLOCK * 4);
    if (blocks > 4736) blocks = 4736;

    gravity_decoder_kernel<<<blocks, THREADS>>>(z, ei, W, b, out, E);
}